// round 13
// baseline (speedup 1.0000x reference)
#include <cuda_runtime.h>
#include <math.h>
#include <cstdint>

#define T    4096
#define S    256
#define NCTA 16       // non-portable cluster size (fits in one GPC on B300)
#define WPC  16       // warps per CTA -> NCTA*WPC == S rows
#define D    8        // publication ring depth (buffers)
#define BP   7        // cluster barrier period (<= D-1 for ring safety)
#define NB   64       // backtrace chunks
#define CH   64       // steps per chunk (NB*CH == T)

// ---- device scratch (no cudaMalloc allowed) ----
__device__ int g_bp[T * S];       // backpointers (filled by sv_bp post-pass)
__device__ int g_link[NB][S];     // composed chunk maps

__device__ __forceinline__ uint32_t smem_u32(const void* p) {
    uint32_t a;
    asm("{ .reg .u64 t; cvta.to.shared.u64 t, %1; cvt.u32.u64 %0, t; }"
        : "=r"(a) : "l"(p));
    return a;
}
__device__ __forceinline__ uint32_t ctarank() {
    uint32_t r;
    asm("mov.u32 %0, %%cluster_ctarank;" : "=r"(r));
    return r;
}
__device__ __forceinline__ uint32_t mapa_u32(uint32_t addr, uint32_t rank) {
    uint32_t rem;
    asm("mapa.shared::cluster.u32 %0, %1, %2;" : "=r"(rem) : "r"(addr), "r"(rank));
    return rem;
}
__device__ __forceinline__ void lds_v2_vol(uint32_t addr,
                                           unsigned long long& a, unsigned long long& b) {
    asm volatile("ld.volatile.shared.v2.u64 {%0,%1}, [%2];"
                 : "=l"(a), "=l"(b) : "r"(addr));
}
__device__ __forceinline__ void st_cluster_u64(uint32_t addr, unsigned long long v) {
    asm volatile("st.shared::cluster.u64 [%0], %1;" :: "r"(addr), "l"(v) : "memory");
}

// ============ sequential DP: LSE only, sentinel-polled tagged publication ============
__global__ __launch_bounds__(512, 1) __cluster_dims__(NCTA, 1, 1)
void sv_dp(const float* __restrict__ pot, float* __restrict__ out) {
    // ring of tagged v buffers: (tag<<32)|f32bits, one full copy per CTA
    __shared__ alignas(16) unsigned long long vbuf[D][S];

    const int tid  = threadIdx.x;
    const int w    = tid >> 5;
    const int lane = tid & 31;
    const uint32_t rank = ctarank();
    const int s    = (int)rank * WPC + w;     // state row owned by this warp
    const bool sentinel = (w == WPC - 1);     // warp 15 polls for everyone
    float* vout = out + T;                    // v[t*S + s]

    // init all tags to invalid
    for (int i = tid; i < D * S; i += 512)
        ((unsigned long long*)vbuf)[i] = ~0ULL;
    if (rank == 0 && tid < S) vout[tid] = pot[tid];   // v0 row of output
    __syncthreads();
    // all CTAs' rings initialized before any remote store may land
    asm volatile("barrier.cluster.arrive.aligned;" ::: "memory");
    asm volatile("barrier.cluster.wait.aligned;" ::: "memory");

    const float* prow = pot + (size_t)s * S;
    const int c0 = 4 * lane;          // columns c0..c0+3
    const int c1 = 128 + 4 * lane;    // columns c1..c1+3

    float K = pot[s];                 // K-shift base = own previous v

    // remote base address of ring slot [0][s] in CTA 'lane'
    uint32_t rem_base = 0;
    if (lane < NCTA)
        rem_base = mapa_u32(smem_u32(&vbuf[0][s]), (uint32_t)lane);
    // local addresses for this lane's 4 vector loads (poll & value reads share layout)
    const uint32_t lb = smem_u32(&vbuf[0][0]);
    const uint32_t la0 = lb + (uint32_t)c0 * 8u;
    const uint32_t la1 = lb + (uint32_t)(c0 + 2) * 8u;
    const uint32_t la2 = lb + (uint32_t)c1 * 8u;
    const uint32_t la3 = lb + (uint32_t)(c1 + 2) * 8u;

    // publish v0 (tag 0) into all CTAs' ring slot 0
    if (lane < NCTA)
        st_cluster_u64(rem_base, (unsigned long long)__float_as_uint(K));

    // prefetch pot for t = 1
    float4 pA = *(const float4*)(prow + (size_t)S * S + c0);
    float4 pB = *(const float4*)(prow + (size_t)S * S + c1);

    int bc = 0;
    for (int t = 1; t < T; ++t) {
        // prefetch for t+1 (lands during wait/compute)
        const size_t nxt = (size_t)((t + 1 < T) ? (t + 1) : t) * S * S;
        float4 nA = *(const float4*)(prow + nxt + c0);
        float4 nB = *(const float4*)(prow + nxt + c1);

        const uint32_t bo = (uint32_t)((t - 1) & (D - 1)) * (S * 8u);
        const unsigned tg = (unsigned)(t - 1);

        // sentinel polls all 256 tags of slot (t-1); workers just wait at the bar
        if (sentinel) {
            unsigned long long x0, x1, x2, x3, y0, y1, y2, y3;
            for (;;) {
                lds_v2_vol(la0 + bo, x0, x1);
                lds_v2_vol(la1 + bo, x2, x3);
                lds_v2_vol(la2 + bo, y0, y1);
                lds_v2_vol(la3 + bo, y2, y3);
                bool ok = ((unsigned)(x0 >> 32) == tg) & ((unsigned)(x1 >> 32) == tg) &
                          ((unsigned)(x2 >> 32) == tg) & ((unsigned)(x3 >> 32) == tg) &
                          ((unsigned)(y0 >> 32) == tg) & ((unsigned)(y1 >> 32) == tg) &
                          ((unsigned)(y2 >> 32) == tg) & ((unsigned)(y3 >> 32) == tg);
                if (__all_sync(0xffffffffu, ok)) break;
            }
        }
        __syncthreads();   // sentinel arrives last -> releases everyone

        // read v_{t-1} values from local ring slot
        unsigned long long a0, a1, a2, a3, b0, b1, b2, b3;
        lds_v2_vol(la0 + bo, a0, a1);
        lds_v2_vol(la1 + bo, a2, a3);
        lds_v2_vol(la2 + bo, b0, b1);
        lds_v2_vol(la3 + bo, b2, b3);

        // scores and exps (K-shift: no max dependency)
        float e = __expf(__uint_as_float((unsigned)a0) + pA.x - K) +
                  __expf(__uint_as_float((unsigned)a1) + pA.y - K) +
                  __expf(__uint_as_float((unsigned)a2) + pA.z - K) +
                  __expf(__uint_as_float((unsigned)a3) + pA.w - K) +
                  __expf(__uint_as_float((unsigned)b0) + pB.x - K) +
                  __expf(__uint_as_float((unsigned)b1) + pB.y - K) +
                  __expf(__uint_as_float((unsigned)b2) + pB.z - K) +
                  __expf(__uint_as_float((unsigned)b3) + pB.w - K);

        // warp sum (5-level shfl tree)
        #pragma unroll
        for (int o = 16; o; o >>= 1)
            e += __shfl_xor_sync(0xffffffffu, e, o);

        float v = K + __logf(e);      // all lanes have v

        // publish v_t[s] into all 16 CTAs' ring slot t&7 (single 8B atom: tag+value)
        const unsigned long long pack =
            ((unsigned long long)(unsigned)t << 32) |
            (unsigned long long)__float_as_uint(v);
        if (lane < NCTA)
            st_cluster_u64(rem_base + (uint32_t)(t & (D - 1)) * (S * 8u), pack);
        if (lane == 0) vout[(size_t)t * S + s] = v;

        // ring-safety barrier every BP steps
        if (++bc == BP) {
            asm volatile("barrier.cluster.arrive.aligned;" ::: "memory");
            asm volatile("barrier.cluster.wait.aligned;" ::: "memory");
            bc = 0;
        }

        K = v;
        pA = nA; pB = nB;
    }

    // no CTA may exit while peers might still store into its SMEM
    asm volatile("barrier.cluster.arrive.aligned;" ::: "memory");
    asm volatile("barrier.cluster.wait.aligned;" ::: "memory");
}

// ============ parallel backpointer recompute ============
// bp[t][s] = argmax_{s'} (v[t-1][s'] + pot[t][s][s']), first-index tie-break
__global__ __launch_bounds__(256, 4)
void sv_bp(const float* __restrict__ pot, const float* __restrict__ out) {
    __shared__ float vprev[S];
    const int t    = (int)blockIdx.x + 1;
    const int tid  = threadIdx.x;
    const int w    = tid >> 5;
    const int lane = tid & 31;
    const float* vout = out + T;

    if (tid < S)
        vprev[tid] = (t == 1) ? pot[tid] : vout[(size_t)(t - 1) * S + tid];
    __syncthreads();

    const int c0 = 4 * lane;
    const int c1 = 128 + 4 * lane;
    float4 vA = *(const float4*)(vprev + c0);
    float4 vB = *(const float4*)(vprev + c1);

    for (int r = 0; r < 32; ++r) {
        const int s = w * 32 + r;
        const float* prow = pot + (size_t)t * S * S + (size_t)s * S;
        float4 pA = *(const float4*)(prow + c0);
        float4 pB = *(const float4*)(prow + c1);

        float sc[8];
        sc[0] = vA.x + pA.x;  sc[1] = vA.y + pA.y;
        sc[2] = vA.z + pA.z;  sc[3] = vA.w + pA.w;
        sc[4] = vB.x + pB.x;  sc[5] = vB.y + pB.y;
        sc[6] = vB.z + pB.z;  sc[7] = vB.w + pB.w;

        float m = sc[0]; int mi = c0;
        #pragma unroll
        for (int k = 1; k < 8; ++k) {
            int c = (k < 4) ? (c0 + k) : (c1 + (k - 4));
            if (sc[k] > m) { m = sc[k]; mi = c; }
        }
        #pragma unroll
        for (int o = 16; o; o >>= 1) {
            float om = __shfl_xor_sync(0xffffffffu, m, o);
            int   oi = __shfl_xor_sync(0xffffffffu, mi, o);
            if (om > m || (om == m && oi < mi)) { m = om; mi = oi; }
        }
        if (lane == 0) g_bp[t * S + s] = mi;
    }
}

// compose each chunk's backpointer map
__global__ void sv_link() {
    int b = blockIdx.x;
    if (b == 0) return;
    int cur = threadIdx.x;
    int tlo = b * CH;
    for (int t = tlo + CH - 2; t >= tlo - 1; --t)
        cur = g_bp[(t + 1) * S + cur];
    g_link[b][threadIdx.x] = cur;
}

__global__ void sv_back(float* __restrict__ out) {
    __shared__ float sm[8];
    __shared__ int   si[8];
    __shared__ int   sE[NB];
    const int tid = threadIdx.x, lane = tid & 31;

    const float* vlast = out + T + (size_t)(T - 1) * S;
    float m = vlast[tid]; int mi = tid;
    #pragma unroll
    for (int o = 16; o; o >>= 1) {
        float om = __shfl_xor_sync(0xffffffffu, m, o);
        int   oi = __shfl_xor_sync(0xffffffffu, mi, o);
        if (om > m || (om == m && oi < mi)) { m = om; mi = oi; }
    }
    if (lane == 0) { sm[tid >> 5] = m; si[tid >> 5] = mi; }
    __syncthreads();

    if (tid == 0) {
        m = sm[0]; mi = si[0];
        #pragma unroll
        for (int w = 1; w < 8; ++w)
            if (sm[w] > m || (sm[w] == m && si[w] < mi)) { m = sm[w]; mi = si[w]; }
        int e = mi;
        sE[NB - 1] = e;
        for (int b = NB - 1; b >= 1; --b) { e = g_link[b][e]; sE[b - 1] = e; }
    }
    __syncthreads();

    if (tid < NB) {
        int b = tid;
        int cur = sE[b];
        out[b * CH + CH - 1] = (float)cur;
        for (int t = b * CH + CH - 2; t >= b * CH; --t) {
            cur = g_bp[(t + 1) * S + cur];
            out[t] = (float)cur;
        }
    }
}

extern "C" void kernel_launch(void* const* d_in, const int* in_sizes, int n_in,
                              void* d_out, int out_size) {
    const float* pot = (const float*)d_in[0];
    float* out = (float*)d_out;

    // allow the 16-CTA non-portable cluster (idempotent, capture-legal)
    cudaFuncSetAttribute(sv_dp, cudaFuncAttributeNonPortableClusterSizeAllowed, 1);

    sv_dp<<<NCTA, 512>>>(pot, out);
    sv_bp<<<T - 1, 256>>>(pot, out);
    sv_link<<<NB, 256>>>();
    sv_back<<<1, 256>>>(out);
}

// round 14
// speedup vs baseline: 1.7206x; 1.7206x over previous
#include <cuda_runtime.h>
#include <math.h>
#include <cstdint>

#define T    4096
#define S    256
#define NCTA 16       // non-portable cluster size
#define WPC  8        // warps per CTA; each warp owns 2 state rows
#define D    16       // publication ring depth
#define BP   15       // cluster barrier period (<= D-1 for ring safety)
#define NB   64       // backtrace chunks
#define CH   64       // steps per chunk (NB*CH == T)

// ---- device scratch (no cudaMalloc allowed) ----
__device__ int g_bp[T * S];       // backpointers (filled by sv_bp post-pass)
__device__ int g_link[NB][S];     // composed chunk maps

__device__ __forceinline__ uint32_t smem_u32(const void* p) {
    uint32_t a;
    asm("{ .reg .u64 t; cvta.to.shared.u64 t, %1; cvt.u32.u64 %0, t; }"
        : "=r"(a) : "l"(p));
    return a;
}
__device__ __forceinline__ uint32_t ctarank() {
    uint32_t r;
    asm("mov.u32 %0, %%cluster_ctarank;" : "=r"(r));
    return r;
}
__device__ __forceinline__ uint32_t mapa_u32(uint32_t addr, uint32_t rank) {
    uint32_t rem;
    asm("mapa.shared::cluster.u32 %0, %1, %2;" : "=r"(rem) : "r"(addr), "r"(rank));
    return rem;
}
__device__ __forceinline__ void lds_v2_vol(uint32_t addr,
                                           unsigned long long& a, unsigned long long& b) {
    asm volatile("ld.volatile.shared.v2.u64 {%0,%1}, [%2];"
                 : "=l"(a), "=l"(b) : "r"(addr));
}
__device__ __forceinline__ void st_cluster_v2u64(uint32_t addr,
                                                 unsigned long long a, unsigned long long b) {
    asm volatile("st.shared::cluster.v2.u64 [%0], {%1,%2};"
                 :: "r"(addr), "l"(a), "l"(b) : "memory");
}

// ============ sequential DP: LSE only, tagged-word publication ============
__global__ __launch_bounds__(256, 1) __cluster_dims__(NCTA, 1, 1)
void sv_dp(const float* __restrict__ pot, float* __restrict__ out) {
    // ring of tagged v buffers: (tag<<32)|f32bits, full copy per CTA (32 KB)
    __shared__ alignas(16) unsigned long long vbuf[D][S];

    const int tid  = threadIdx.x;
    const int w    = tid >> 5;
    const int lane = tid & 31;
    const uint32_t rank = ctarank();
    const int s0   = ((int)rank * WPC + w) * 2;   // this warp's two state rows
    const int s1   = s0 + 1;
    float* vout = out + T;                        // v[t*S + s]

    // init all tags to invalid
    for (int i = tid; i < D * S; i += 256)
        ((unsigned long long*)vbuf)[i] = ~0ULL;
    if (rank == 0 && tid < S) vout[tid] = pot[tid];   // v0 row of output
    __syncthreads();
    // all CTAs' rings initialized before any remote store may land
    asm volatile("barrier.cluster.arrive.aligned;" ::: "memory");
    asm volatile("barrier.cluster.wait.aligned;" ::: "memory");

    const float* prow0 = pot + (size_t)s0 * S;
    const float* prow1 = pot + (size_t)s1 * S;
    const int c0 = 4 * lane;          // columns c0..c0+3
    const int c1 = 128 + 4 * lane;    // columns c1..c1+3

    float K0 = pot[s0];               // K-shift bases = own previous v
    float K1 = pot[s1];

    // remote base address of ring slot [0][s0] in CTA 'lane' (16B aligned, s0 even)
    uint32_t rem_base = 0;
    if (lane < NCTA)
        rem_base = mapa_u32(smem_u32(&vbuf[0][s0]), (uint32_t)lane);
    // local poll/value addresses for this lane's 4 vector loads
    const uint32_t lb = smem_u32(&vbuf[0][0]);
    const uint32_t la0 = lb + (uint32_t)c0 * 8u;
    const uint32_t la1 = lb + (uint32_t)(c0 + 2) * 8u;
    const uint32_t la2 = lb + (uint32_t)c1 * 8u;
    const uint32_t la3 = lb + (uint32_t)(c1 + 2) * 8u;

    // publish v0 (tag 0) for both rows in one 16B message per target CTA
    if (lane < NCTA)
        st_cluster_v2u64(rem_base,
                         (unsigned long long)__float_as_uint(K0),
                         (unsigned long long)__float_as_uint(K1));

    // prefetch pot rows for t = 1
    float4 pA0 = *(const float4*)(prow0 + (size_t)S * S + c0);
    float4 pB0 = *(const float4*)(prow0 + (size_t)S * S + c1);
    float4 pA1 = *(const float4*)(prow1 + (size_t)S * S + c0);
    float4 pB1 = *(const float4*)(prow1 + (size_t)S * S + c1);

    int bc = 0;
    for (int t = 1; t < T; ++t) {
        // prefetch for t+1 (lands during poll/compute)
        const size_t nxt = (size_t)((t + 1 < T) ? (t + 1) : t) * S * S;
        float4 nA0 = *(const float4*)(prow0 + nxt + c0);
        float4 nB0 = *(const float4*)(prow0 + nxt + c1);
        float4 nA1 = *(const float4*)(prow1 + nxt + c0);
        float4 nB1 = *(const float4*)(prow1 + nxt + c1);

        // poll local ring slot (t-1)%D until all 8 tags == t-1
        const uint32_t bo = (uint32_t)((t - 1) & (D - 1)) * (S * 8u);
        const unsigned tg = (unsigned)(t - 1);
        unsigned long long a0, a1, a2, a3, b0, b1, b2, b3;
        for (;;) {
            lds_v2_vol(la0 + bo, a0, a1);
            lds_v2_vol(la1 + bo, a2, a3);
            lds_v2_vol(la2 + bo, b0, b1);
            lds_v2_vol(la3 + bo, b2, b3);
            bool ok = ((unsigned)(a0 >> 32) == tg) & ((unsigned)(a1 >> 32) == tg) &
                      ((unsigned)(a2 >> 32) == tg) & ((unsigned)(a3 >> 32) == tg) &
                      ((unsigned)(b0 >> 32) == tg) & ((unsigned)(b1 >> 32) == tg) &
                      ((unsigned)(b2 >> 32) == tg) & ((unsigned)(b3 >> 32) == tg);
            if (__all_sync(0xffffffffu, ok)) break;
        }

        const float v0a = __uint_as_float((unsigned)a0);
        const float v1a = __uint_as_float((unsigned)a1);
        const float v2a = __uint_as_float((unsigned)a2);
        const float v3a = __uint_as_float((unsigned)a3);
        const float v0b = __uint_as_float((unsigned)b0);
        const float v1b = __uint_as_float((unsigned)b1);
        const float v2b = __uint_as_float((unsigned)b2);
        const float v3b = __uint_as_float((unsigned)b3);

        // row s0 and row s1 exps (K-shift: no max dependency)
        float e0 = __expf(v0a + pA0.x - K0) + __expf(v1a + pA0.y - K0) +
                   __expf(v2a + pA0.z - K0) + __expf(v3a + pA0.w - K0) +
                   __expf(v0b + pB0.x - K0) + __expf(v1b + pB0.y - K0) +
                   __expf(v2b + pB0.z - K0) + __expf(v3b + pB0.w - K0);
        float e1 = __expf(v0a + pA1.x - K1) + __expf(v1a + pA1.y - K1) +
                   __expf(v2a + pA1.z - K1) + __expf(v3a + pA1.w - K1) +
                   __expf(v0b + pB1.x - K1) + __expf(v1b + pB1.y - K1) +
                   __expf(v2b + pB1.z - K1) + __expf(v3b + pB1.w - K1);

        // two independent shfl sum chains (pipelined)
        #pragma unroll
        for (int o = 16; o; o >>= 1) {
            e0 += __shfl_xor_sync(0xffffffffu, e0, o);
            e1 += __shfl_xor_sync(0xffffffffu, e1, o);
        }

        float v0 = K0 + __logf(e0);
        float v1 = K1 + __logf(e1);

        // publish both rows (one 16B message per target CTA; 8B atoms carry tag+value)
        const unsigned long long tagw = (unsigned long long)(unsigned)t << 32;
        if (lane < NCTA)
            st_cluster_v2u64(rem_base + (uint32_t)(t & (D - 1)) * (S * 8u),
                             tagw | (unsigned long long)__float_as_uint(v0),
                             tagw | (unsigned long long)__float_as_uint(v1));
        if (lane == 0) {
            vout[(size_t)t * S + s0] = v0;
            vout[(size_t)t * S + s1] = v1;
        }

        // ring-safety barrier every BP steps
        if (++bc == BP) {
            asm volatile("barrier.cluster.arrive.aligned;" ::: "memory");
            asm volatile("barrier.cluster.wait.aligned;" ::: "memory");
            bc = 0;
        }

        K0 = v0; K1 = v1;
        pA0 = nA0; pB0 = nB0; pA1 = nA1; pB1 = nB1;
    }

    // no CTA may exit while peers might still store into its SMEM
    asm volatile("barrier.cluster.arrive.aligned;" ::: "memory");
    asm volatile("barrier.cluster.wait.aligned;" ::: "memory");
}

// ============ parallel backpointer recompute ============
// bp[t][s] = argmax_{s'} (v[t-1][s'] + pot[t][s][s']), first-index tie-break
__global__ __launch_bounds__(256, 4)
void sv_bp(const float* __restrict__ pot, const float* __restrict__ out) {
    __shared__ float vprev[S];
    const int t    = (int)blockIdx.x + 1;
    const int tid  = threadIdx.x;
    const int w    = tid >> 5;
    const int lane = tid & 31;
    const float* vout = out + T;

    if (tid < S)
        vprev[tid] = (t == 1) ? pot[tid] : vout[(size_t)(t - 1) * S + tid];
    __syncthreads();

    const int c0 = 4 * lane;
    const int c1 = 128 + 4 * lane;
    float4 vA = *(const float4*)(vprev + c0);
    float4 vB = *(const float4*)(vprev + c1);

    for (int r = 0; r < 32; ++r) {
        const int s = w * 32 + r;
        const float* prow = pot + (size_t)t * S * S + (size_t)s * S;
        float4 pA = *(const float4*)(prow + c0);
        float4 pB = *(const float4*)(prow + c1);

        float sc[8];
        sc[0] = vA.x + pA.x;  sc[1] = vA.y + pA.y;
        sc[2] = vA.z + pA.z;  sc[3] = vA.w + pA.w;
        sc[4] = vB.x + pB.x;  sc[5] = vB.y + pB.y;
        sc[6] = vB.z + pB.z;  sc[7] = vB.w + pB.w;

        float m = sc[0]; int mi = c0;
        #pragma unroll
        for (int k = 1; k < 8; ++k) {
            int c = (k < 4) ? (c0 + k) : (c1 + (k - 4));
            if (sc[k] > m) { m = sc[k]; mi = c; }
        }
        #pragma unroll
        for (int o = 16; o; o >>= 1) {
            float om = __shfl_xor_sync(0xffffffffu, m, o);
            int   oi = __shfl_xor_sync(0xffffffffu, mi, o);
            if (om > m || (om == m && oi < mi)) { m = om; mi = oi; }
        }
        if (lane == 0) g_bp[t * S + s] = mi;
    }
}

// compose each chunk's backpointer map
__global__ void sv_link() {
    int b = blockIdx.x;
    if (b == 0) return;
    int cur = threadIdx.x;
    int tlo = b * CH;
    for (int t = tlo + CH - 2; t >= tlo - 1; --t)
        cur = g_bp[(t + 1) * S + cur];
    g_link[b][threadIdx.x] = cur;
}

__global__ void sv_back(float* __restrict__ out) {
    __shared__ float sm[8];
    __shared__ int   si[8];
    __shared__ int   sE[NB];
    const int tid = threadIdx.x, lane = tid & 31;

    const float* vlast = out + T + (size_t)(T - 1) * S;
    float m = vlast[tid]; int mi = tid;
    #pragma unroll
    for (int o = 16; o; o >>= 1) {
        float om = __shfl_xor_sync(0xffffffffu, m, o);
        int   oi = __shfl_xor_sync(0xffffffffu, mi, o);
        if (om > m || (om == m && oi < mi)) { m = om; mi = oi; }
    }
    if (lane == 0) { sm[tid >> 5] = m; si[tid >> 5] = mi; }
    __syncthreads();

    if (tid == 0) {
        m = sm[0]; mi = si[0];
        #pragma unroll
        for (int w = 1; w < 8; ++w)
            if (sm[w] > m || (sm[w] == m && si[w] < mi)) { m = sm[w]; mi = si[w]; }
        int e = mi;
        sE[NB - 1] = e;
        for (int b = NB - 1; b >= 1; --b) { e = g_link[b][e]; sE[b - 1] = e; }
    }
    __syncthreads();

    if (tid < NB) {
        int b = tid;
        int cur = sE[b];
        out[b * CH + CH - 1] = (float)cur;
        for (int t = b * CH + CH - 2; t >= b * CH; --t) {
            cur = g_bp[(t + 1) * S + cur];
            out[t] = (float)cur;
        }
    }
}

extern "C" void kernel_launch(void* const* d_in, const int* in_sizes, int n_in,
                              void* d_out, int out_size) {
    const float* pot = (const float*)d_in[0];
    float* out = (float*)d_out;

    // allow the 16-CTA non-portable cluster (idempotent, capture-legal)
    cudaFuncSetAttribute(sv_dp, cudaFuncAttributeNonPortableClusterSizeAllowed, 1);

    sv_dp<<<NCTA, 256>>>(pot, out);
    sv_bp<<<T - 1, 256>>>(pot, out);
    sv_link<<<NB, 256>>>();
    sv_back<<<1, 256>>>(out);
}

// round 16
// speedup vs baseline: 1.8707x; 1.0872x over previous
#include <cuda_runtime.h>
#include <math.h>
#include <cstdint>

#define T    4096
#define S    256
#define NCTA 16       // non-portable cluster size
#define WPC  4        // warps per CTA; each warp owns 4 state rows
#define D    16       // publication ring depth (tag protocol alone is safe; D>=2)
#define NB   64       // backtrace chunks
#define CH   64       // steps per chunk (NB*CH == T)

// ---- device scratch (no cudaMalloc allowed) ----
__device__ int g_bp[T * S];       // backpointers (filled by sv_bp post-pass)
__device__ int g_link[NB][S];     // composed chunk maps

__device__ __forceinline__ uint32_t smem_u32(const void* p) {
    uint32_t a;
    asm("{ .reg .u64 t; cvta.to.shared.u64 t, %1; cvt.u32.u64 %0, t; }"
        : "=r"(a) : "l"(p));
    return a;
}
__device__ __forceinline__ uint32_t ctarank() {
    uint32_t r;
    asm("mov.u32 %0, %%cluster_ctarank;" : "=r"(r));
    return r;
}
__device__ __forceinline__ uint32_t mapa_u32(uint32_t addr, uint32_t rank) {
    uint32_t rem;
    asm("mapa.shared::cluster.u32 %0, %1, %2;" : "=r"(rem) : "r"(addr), "r"(rank));
    return rem;
}
__device__ __forceinline__ void lds_v2_vol(uint32_t addr,
                                           unsigned long long& a, unsigned long long& b) {
    asm volatile("ld.volatile.shared.v2.u64 {%0,%1}, [%2];"
                 : "=l"(a), "=l"(b) : "r"(addr));
}
__device__ __forceinline__ void st_cluster_v2u64(uint32_t addr,
                                                 unsigned long long a, unsigned long long b) {
    asm volatile("st.shared::cluster.v2.u64 [%0], {%1,%2};"
                 :: "r"(addr), "l"(a), "l"(b) : "memory");
}

// ============ sequential DP: LSE only, tagged-word publication ============
// Numerics per row are IDENTICAL to the proven R14 kernel:
//   e_r = sum_{j in lane's 8 cols} __expf(v_j + p_rj - K_r)  (fixed order)
//   warp shfl-xor sum tree, v_r = K_r + __logf(e_r)
__global__ __launch_bounds__(128, 1) __cluster_dims__(NCTA, 1, 1)
void sv_dp(const float* __restrict__ pot, float* __restrict__ out) {
    // ring of tagged v buffers: (tag<<32)|f32bits, full copy per CTA (32 KB)
    __shared__ alignas(16) unsigned long long vbuf[D][S];

    const int tid  = threadIdx.x;
    const int w    = tid >> 5;
    const int lane = tid & 31;
    const uint32_t rank = ctarank();
    const int s0   = ((int)rank * WPC + w) * 4;   // this warp's four state rows
    float* vout = out + T;                        // v[t*S + s]

    // init all tags to invalid
    for (int i = tid; i < D * S; i += 128)
        ((unsigned long long*)vbuf)[i] = ~0ULL;
    if (rank == 0)
        for (int i = tid; i < S; i += 128) vout[i] = pot[i];   // v0 row of output
    __syncthreads();
    // all CTAs' rings initialized before any remote store may land
    asm volatile("barrier.cluster.arrive.aligned;" ::: "memory");
    asm volatile("barrier.cluster.wait.aligned;" ::: "memory");

    const float* prow0 = pot + (size_t)(s0 + 0) * S;
    const float* prow1 = pot + (size_t)(s0 + 1) * S;
    const float* prow2 = pot + (size_t)(s0 + 2) * S;
    const float* prow3 = pot + (size_t)(s0 + 3) * S;
    const int c0 = 4 * lane;          // columns c0..c0+3
    const int c1 = 128 + 4 * lane;    // columns c1..c1+3

    float K0 = pot[s0], K1 = pot[s0 + 1], K2 = pot[s0 + 2], K3 = pot[s0 + 3];

    // remote base address of ring slot [0][s0] in CTA 'lane' (32B aligned: s0 % 4 == 0)
    uint32_t rem_base = 0;
    if (lane < NCTA)
        rem_base = mapa_u32(smem_u32(&vbuf[0][s0]), (uint32_t)lane);
    // local poll/value addresses for this lane's 4 vector loads
    const uint32_t lb = smem_u32(&vbuf[0][0]);
    const uint32_t la0 = lb + (uint32_t)c0 * 8u;
    const uint32_t la1 = lb + (uint32_t)(c0 + 2) * 8u;
    const uint32_t la2 = lb + (uint32_t)c1 * 8u;
    const uint32_t la3 = lb + (uint32_t)(c1 + 2) * 8u;

    // publish v0 (tag 0) for all four rows: two 16B messages per target CTA
    if (lane < NCTA) {
        st_cluster_v2u64(rem_base,
                         (unsigned long long)__float_as_uint(K0),
                         (unsigned long long)__float_as_uint(K1));
        st_cluster_v2u64(rem_base + 16,
                         (unsigned long long)__float_as_uint(K2),
                         (unsigned long long)__float_as_uint(K3));
    }

    // prefetch pot rows for t = 1
    float4 pA0 = *(const float4*)(prow0 + (size_t)S * S + c0);
    float4 pB0 = *(const float4*)(prow0 + (size_t)S * S + c1);
    float4 pA1 = *(const float4*)(prow1 + (size_t)S * S + c0);
    float4 pB1 = *(const float4*)(prow1 + (size_t)S * S + c1);
    float4 pA2 = *(const float4*)(prow2 + (size_t)S * S + c0);
    float4 pB2 = *(const float4*)(prow2 + (size_t)S * S + c1);
    float4 pA3 = *(const float4*)(prow3 + (size_t)S * S + c0);
    float4 pB3 = *(const float4*)(prow3 + (size_t)S * S + c1);

    for (int t = 1; t < T; ++t) {
        // prefetch pot for t+1 (lands during poll/compute)
        const size_t nxt = (size_t)((t + 1 < T) ? (t + 1) : t) * S * S;
        float4 nA0 = *(const float4*)(prow0 + nxt + c0);
        float4 nB0 = *(const float4*)(prow0 + nxt + c1);
        float4 nA1 = *(const float4*)(prow1 + nxt + c0);
        float4 nB1 = *(const float4*)(prow1 + nxt + c1);
        float4 nA2 = *(const float4*)(prow2 + nxt + c0);
        float4 nB2 = *(const float4*)(prow2 + nxt + c1);
        float4 nA3 = *(const float4*)(prow3 + nxt + c0);
        float4 nB3 = *(const float4*)(prow3 + nxt + c1);

        // poll local ring slot (t-1)%D until all 8 tags == t-1
        const uint32_t bo = (uint32_t)((t - 1) & (D - 1)) * (S * 8u);
        const unsigned tg = (unsigned)(t - 1);
        unsigned long long a0, a1, a2, a3, b0, b1, b2, b3;
        for (;;) {
            lds_v2_vol(la0 + bo, a0, a1);
            lds_v2_vol(la1 + bo, a2, a3);
            lds_v2_vol(la2 + bo, b0, b1);
            lds_v2_vol(la3 + bo, b2, b3);
            bool ok = ((unsigned)(a0 >> 32) == tg) & ((unsigned)(a1 >> 32) == tg) &
                      ((unsigned)(a2 >> 32) == tg) & ((unsigned)(a3 >> 32) == tg) &
                      ((unsigned)(b0 >> 32) == tg) & ((unsigned)(b1 >> 32) == tg) &
                      ((unsigned)(b2 >> 32) == tg) & ((unsigned)(b3 >> 32) == tg);
            if (__all_sync(0xffffffffu, ok)) break;
        }

        const float v0a = __uint_as_float((unsigned)a0);
        const float v1a = __uint_as_float((unsigned)a1);
        const float v2a = __uint_as_float((unsigned)a2);
        const float v3a = __uint_as_float((unsigned)a3);
        const float v0b = __uint_as_float((unsigned)b0);
        const float v1b = __uint_as_float((unsigned)b1);
        const float v2b = __uint_as_float((unsigned)b2);
        const float v3b = __uint_as_float((unsigned)b3);

        // per-row direct exps, EXACT R14 order (numerically pinned)
        float e0 = __expf(v0a + pA0.x - K0) + __expf(v1a + pA0.y - K0) +
                   __expf(v2a + pA0.z - K0) + __expf(v3a + pA0.w - K0) +
                   __expf(v0b + pB0.x - K0) + __expf(v1b + pB0.y - K0) +
                   __expf(v2b + pB0.z - K0) + __expf(v3b + pB0.w - K0);
        float e1 = __expf(v0a + pA1.x - K1) + __expf(v1a + pA1.y - K1) +
                   __expf(v2a + pA1.z - K1) + __expf(v3a + pA1.w - K1) +
                   __expf(v0b + pB1.x - K1) + __expf(v1b + pB1.y - K1) +
                   __expf(v2b + pB1.z - K1) + __expf(v3b + pB1.w - K1);
        float e2 = __expf(v0a + pA2.x - K2) + __expf(v1a + pA2.y - K2) +
                   __expf(v2a + pA2.z - K2) + __expf(v3a + pA2.w - K2) +
                   __expf(v0b + pB2.x - K2) + __expf(v1b + pB2.y - K2) +
                   __expf(v2b + pB2.z - K2) + __expf(v3b + pB2.w - K2);
        float e3 = __expf(v0a + pA3.x - K3) + __expf(v1a + pA3.y - K3) +
                   __expf(v2a + pA3.z - K3) + __expf(v3a + pA3.w - K3) +
                   __expf(v0b + pB3.x - K3) + __expf(v1b + pB3.y - K3) +
                   __expf(v2b + pB3.z - K3) + __expf(v3b + pB3.w - K3);

        // four interleaved shfl sum chains (same tree as R14 per chain)
        #pragma unroll
        for (int o = 16; o; o >>= 1) {
            e0 += __shfl_xor_sync(0xffffffffu, e0, o);
            e1 += __shfl_xor_sync(0xffffffffu, e1, o);
            e2 += __shfl_xor_sync(0xffffffffu, e2, o);
            e3 += __shfl_xor_sync(0xffffffffu, e3, o);
        }

        float v0 = K0 + __logf(e0);
        float v1 = K1 + __logf(e1);
        float v2 = K2 + __logf(e2);
        float v3 = K3 + __logf(e3);

        // publish all four rows: two 16B messages per target CTA
        const unsigned long long tagw = (unsigned long long)(unsigned)t << 32;
        const uint32_t off = (uint32_t)(t & (D - 1)) * (S * 8u);
        if (lane < NCTA) {
            st_cluster_v2u64(rem_base + off,
                             tagw | (unsigned long long)__float_as_uint(v0),
                             tagw | (unsigned long long)__float_as_uint(v1));
            st_cluster_v2u64(rem_base + off + 16,
                             tagw | (unsigned long long)__float_as_uint(v2),
                             tagw | (unsigned long long)__float_as_uint(v3));
        }
        if (lane == 0)
            *(float4*)(vout + (size_t)t * S + s0) = make_float4(v0, v1, v2, v3);

        K0 = v0; K1 = v1; K2 = v2; K3 = v3;
        pA0 = nA0; pB0 = nB0; pA1 = nA1; pB1 = nB1;
        pA2 = nA2; pB2 = nB2; pA3 = nA3; pB3 = nB3;
        // NOTE: no periodic barrier needed — the tag protocol alone prevents
        // slot reuse races (writer at t required all tags t-1, so every warp
        // already finished reading slot t-16).
    }

    // no CTA may exit while peers might still store into its SMEM
    asm volatile("barrier.cluster.arrive.aligned;" ::: "memory");
    asm volatile("barrier.cluster.wait.aligned;" ::: "memory");
}

// ============ parallel backpointer recompute ============
// bp[t][s] = argmax_{s'} (v[t-1][s'] + pot[t][s][s']), first-index tie-break
__global__ __launch_bounds__(256, 4)
void sv_bp(const float* __restrict__ pot, const float* __restrict__ out) {
    __shared__ float vprev[S];
    const int t    = (int)blockIdx.x + 1;
    const int tid  = threadIdx.x;
    const int w    = tid >> 5;
    const int lane = tid & 31;
    const float* vout = out + T;

    if (tid < S)
        vprev[tid] = (t == 1) ? pot[tid] : vout[(size_t)(t - 1) * S + tid];
    __syncthreads();

    const int c0 = 4 * lane;
    const int c1 = 128 + 4 * lane;
    float4 vA = *(const float4*)(vprev + c0);
    float4 vB = *(const float4*)(vprev + c1);

    for (int r = 0; r < 32; ++r) {
        const int s = w * 32 + r;
        const float* prow = pot + (size_t)t * S * S + (size_t)s * S;
        float4 pA = *(const float4*)(prow + c0);
        float4 pB = *(const float4*)(prow + c1);

        float sc[8];
        sc[0] = vA.x + pA.x;  sc[1] = vA.y + pA.y;
        sc[2] = vA.z + pA.z;  sc[3] = vA.w + pA.w;
        sc[4] = vB.x + pB.x;  sc[5] = vB.y + pB.y;
        sc[6] = vB.z + pB.z;  sc[7] = vB.w + pB.w;

        float m = sc[0]; int mi = c0;
        #pragma unroll
        for (int k = 1; k < 8; ++k) {
            int c = (k < 4) ? (c0 + k) : (c1 + (k - 4));
            if (sc[k] > m) { m = sc[k]; mi = c; }
        }
        #pragma unroll
        for (int o = 16; o; o >>= 1) {
            float om = __shfl_xor_sync(0xffffffffu, m, o);
            int   oi = __shfl_xor_sync(0xffffffffu, mi, o);
            if (om > m || (om == m && oi < mi)) { m = om; mi = oi; }
        }
        if (lane == 0) g_bp[t * S + s] = mi;
    }
}

// compose each chunk's backpointer map
__global__ void sv_link() {
    int b = blockIdx.x;
    if (b == 0) return;
    int cur = threadIdx.x;
    int tlo = b * CH;
    for (int t = tlo + CH - 2; t >= tlo - 1; --t)
        cur = g_bp[(t + 1) * S + cur];
    g_link[b][threadIdx.x] = cur;
}

__global__ void sv_back(float* __restrict__ out) {
    __shared__ float sm[8];
    __shared__ int   si[8];
    __shared__ int   sE[NB];
    const int tid = threadIdx.x, lane = tid & 31;

    const float* vlast = out + T + (size_t)(T - 1) * S;
    float m = vlast[tid]; int mi = tid;
    #pragma unroll
    for (int o = 16; o; o >>= 1) {
        float om = __shfl_xor_sync(0xffffffffu, m, o);
        int   oi = __shfl_xor_sync(0xffffffffu, mi, o);
        if (om > m || (om == m && oi < mi)) { m = om; mi = oi; }
    }
    if (lane == 0) { sm[tid >> 5] = m; si[tid >> 5] = mi; }
    __syncthreads();

    if (tid == 0) {
        m = sm[0]; mi = si[0];
        #pragma unroll
        for (int w = 1; w < 8; ++w)
            if (sm[w] > m || (sm[w] == m && si[w] < mi)) { m = sm[w]; mi = si[w]; }
        int e = mi;
        sE[NB - 1] = e;
        for (int b = NB - 1; b >= 1; --b) { e = g_link[b][e]; sE[b - 1] = e; }
    }
    __syncthreads();

    if (tid < NB) {
        int b = tid;
        int cur = sE[b];
        out[b * CH + CH - 1] = (float)cur;
        for (int t = b * CH + CH - 2; t >= b * CH; --t) {
            cur = g_bp[(t + 1) * S + cur];
            out[t] = (float)cur;
        }
    }
}

extern "C" void kernel_launch(void* const* d_in, const int* in_sizes, int n_in,
                              void* d_out, int out_size) {
    const float* pot = (const float*)d_in[0];
    float* out = (float*)d_out;

    // allow the 16-CTA non-portable cluster (idempotent, capture-legal)
    cudaFuncSetAttribute(sv_dp, cudaFuncAttributeNonPortableClusterSizeAllowed, 1);

    sv_dp<<<NCTA, 128>>>(pot, out);
    sv_bp<<<T - 1, 256>>>(pot, out);
    sv_link<<<NB, 256>>>();
    sv_back<<<1, 256>>>(out);
}